// round 1
// baseline (speedup 1.0000x reference)
#include <cuda_runtime.h>
#include <math.h>

// ---------------------------------------------------------------------------
// ASE block: B=16, DIM=256, H=W=64, KEY_DIM=16, HEADS=8, NH_KD=128, DH=256
// Pipeline:
//   k_means    : row/col means of x                     -> g_xm
//   k_projmean : q/k/v on means (+scale/bias/pos-embed) -> g_qkm
//   k_attn     : 64-token axial attention (+relu)       -> g_attn
//   k_projattn : Wr / Wc projection                     -> g_xrc
//   k_main     : fused per-pixel: qkv GEMM -> gate GEMM, v_raw+xr+xc -> Wp
//                GEMM -> hsigmoid * gate                -> out
// ---------------------------------------------------------------------------

#define NPIX 4096           // 64*64
#define SLICE (16*256*64)   // one [b][c][pos] slab

__device__ float g_xm  [2*16*256*64];   // [branch][b][c][pos]  means of x
__device__ float g_qkm [2*16*512*64];   // [branch][b][ch][pos] projected means
__device__ float g_attn[2*16*256*64];   // relu(attention out)
__device__ float g_xrc [2*16*256*64];   // final xr (branch0) / xc (branch1)

// ---------------------------------------------------------------------------
// K1: row means (branch0, indexed by h) and col means (branch1, indexed by w)
// grid: 4096 blocks (b*256+c), 64 threads
// ---------------------------------------------------------------------------
__global__ void k_means(const float* __restrict__ x) {
    int bc = blockIdx.x;                       // b*256 + c
    const float* xp = x + (size_t)bc * NPIX;
    int t = threadIdx.x;                       // 0..63  (= w)
    int warp = t >> 5, lane = t & 31;
    __shared__ float rowp[64][2];
    float colacc = 0.f;
    for (int h = 0; h < 64; h++) {
        float v = xp[h*64 + t];
        colacc += v;
        float s = v;
        s += __shfl_xor_sync(0xffffffffu, s, 16);
        s += __shfl_xor_sync(0xffffffffu, s, 8);
        s += __shfl_xor_sync(0xffffffffu, s, 4);
        s += __shfl_xor_sync(0xffffffffu, s, 2);
        s += __shfl_xor_sync(0xffffffffu, s, 1);
        if (lane == 0) rowp[h][warp] = s;
    }
    __syncthreads();
    float rm = (rowp[t][0] + rowp[t][1]) * (1.f/64.f);
    g_xm[(size_t)bc*64 + t]         = rm;                  // branch0: mean over w
    g_xm[SLICE + (size_t)bc*64 + t] = colacc * (1.f/64.f); // branch1: mean over h
}

// ---------------------------------------------------------------------------
// Linear interp of (C,16) positional embed to length-64
// ---------------------------------------------------------------------------
__device__ __forceinline__ float pe_interp(const float* pe, int chan, int p) {
    float pos = fminf(fmaxf((p + 0.5f)*0.25f - 0.5f, 0.f), 15.f);
    int   i0  = (int)pos;
    int   i1  = min(i0 + 1, 15);
    float w   = pos - (float)i0;
    return pe[chan*16 + i0]*(1.f - w) + pe[chan*16 + i1]*w;
}

// ---------------------------------------------------------------------------
// K2a: project means: rows 0..127 q(+pe), 128..255 k(+pe), 256..511 v
// grid: dim3(16 rowchunks, 2 branch, 16 b), 256 threads (32 rows x 8 colgrp)
// ---------------------------------------------------------------------------
__global__ void k_projmean(
    const float* __restrict__ Wq, const float* __restrict__ sq, const float* __restrict__ bq,
    const float* __restrict__ Wk, const float* __restrict__ sk, const float* __restrict__ bk,
    const float* __restrict__ Wv, const float* __restrict__ sv, const float* __restrict__ bv,
    const float* __restrict__ pe_rq, const float* __restrict__ pe_rk,
    const float* __restrict__ pe_cq, const float* __restrict__ pe_ck)
{
    int chunk  = blockIdx.x;
    int branch = blockIdx.y;
    int b      = blockIdx.z;
    int tid = threadIdx.x;
    int r = tid >> 3, cg = tid & 7, col0 = cg*8;
    int grow = chunk*32 + r;                     // 0..511
    __shared__ float xmc[16*64];
    const float* xmbase = g_xm + ((size_t)(branch*16 + b)*256)*64;

    const float* wbase; float sA, bA;
    if (grow < 128)      { wbase = Wq + grow*256;       sA = sq[grow];     bA = bq[grow]; }
    else if (grow < 256) { wbase = Wk + (grow-128)*256; sA = sk[grow-128]; bA = bk[grow-128]; }
    else                 { wbase = Wv + (grow-256)*256; sA = sv[grow-256]; bA = bv[grow-256]; }

    float acc[8];
    #pragma unroll
    for (int j = 0; j < 8; j++) acc[j] = 0.f;

    for (int kc = 0; kc < 16; kc++) {
        #pragma unroll
        for (int t = 0; t < 4; t++) {
            int idx = tid + t*256;
            xmc[idx] = xmbase[(kc*16 + (idx >> 6))*64 + (idx & 63)];
        }
        __syncthreads();
        #pragma unroll
        for (int kk = 0; kk < 16; kk++) {
            float wv = wbase[kc*16 + kk];
            float4 b0 = *(const float4*)&xmc[kk*64 + col0];
            float4 b1 = *(const float4*)&xmc[kk*64 + col0 + 4];
            acc[0] = fmaf(wv, b0.x, acc[0]); acc[1] = fmaf(wv, b0.y, acc[1]);
            acc[2] = fmaf(wv, b0.z, acc[2]); acc[3] = fmaf(wv, b0.w, acc[3]);
            acc[4] = fmaf(wv, b1.x, acc[4]); acc[5] = fmaf(wv, b1.y, acc[5]);
            acc[6] = fmaf(wv, b1.z, acc[6]); acc[7] = fmaf(wv, b1.w, acc[7]);
        }
        __syncthreads();
    }

    float outv[8];
    #pragma unroll
    for (int j = 0; j < 8; j++) outv[j] = fmaf(sA, acc[j], bA);

    if (grow < 256) {
        const float* pe = (branch == 0) ? ((grow < 128) ? pe_rq : pe_rk)
                                        : ((grow < 128) ? pe_cq : pe_ck);
        int chan = (grow < 128) ? grow : grow - 128;
        #pragma unroll
        for (int j = 0; j < 8; j++) outv[j] += pe_interp(pe, chan, col0 + j);
    }
    float* dst = g_qkm + ((size_t)((branch*16 + b)*512 + grow))*64 + col0;
    #pragma unroll
    for (int j = 0; j < 8; j++) dst[j] = outv[j];
}

// ---------------------------------------------------------------------------
// K2b: axial attention per (head, branch, b); 64 threads, thread = query pos
// writes relu(attn_out) to g_attn
// ---------------------------------------------------------------------------
__global__ void k_attn() {
    int head   = blockIdx.x;
    int branch = blockIdx.y;
    int b      = blockIdx.z;
    int i = threadIdx.x;   // 0..63
    __shared__ float kf[16*64];
    __shared__ float vf[32*64];
    const float* base = g_qkm + ((size_t)(branch*16 + b)*512)*64;

    #pragma unroll
    for (int t = 0; t < 16; t++) {
        int idx = i + t*64;
        kf[idx] = base[(128 + head*16 + (idx >> 6))*64 + (idx & 63)];
    }
    #pragma unroll
    for (int t = 0; t < 32; t++) {
        int idx = i + t*64;
        vf[idx] = base[(256 + head*32 + (idx >> 6))*64 + (idx & 63)];
    }
    __syncthreads();

    float qv[16];
    #pragma unroll
    for (int kd = 0; kd < 16; kd++) qv[kd] = base[(head*16 + kd)*64 + i];

    float mx = -1e30f;
    for (int j = 0; j < 64; j++) {
        float s = 0.f;
        #pragma unroll
        for (int kd = 0; kd < 16; kd++) s = fmaf(qv[kd], kf[kd*64 + j], s);
        mx = fmaxf(mx, s * 0.25f);
    }
    float sum = 0.f;
    float facc[32];
    #pragma unroll
    for (int d = 0; d < 32; d++) facc[d] = 0.f;
    for (int j = 0; j < 64; j++) {
        float s = 0.f;
        #pragma unroll
        for (int kd = 0; kd < 16; kd++) s = fmaf(qv[kd], kf[kd*64 + j], s);
        float e = expf(s * 0.25f - mx);
        sum += e;
        #pragma unroll
        for (int d = 0; d < 32; d++) facc[d] = fmaf(e, vf[d*64 + j], facc[d]);
    }
    float inv = 1.f / sum;
    float* dst = g_attn + ((size_t)((branch*16 + b)*256 + head*32))*64 + i;
    #pragma unroll
    for (int d = 0; d < 32; d++) dst[d*64] = fmaxf(facc[d]*inv, 0.f);
}

// ---------------------------------------------------------------------------
// K2c: xr = sr*(Wr @ attn) + br (branch0) ; xc with Wc (branch1)
// grid: dim3(8 rowchunks, 2 branch, 16 b), 256 threads
// ---------------------------------------------------------------------------
__global__ void k_projattn(
    const float* __restrict__ Wr, const float* __restrict__ sr, const float* __restrict__ br,
    const float* __restrict__ Wc, const float* __restrict__ sc, const float* __restrict__ bc)
{
    int chunk  = blockIdx.x;
    int branch = blockIdx.y;
    int b      = blockIdx.z;
    int tid = threadIdx.x;
    int r = tid >> 3, cg = tid & 7, col0 = cg*8;
    int grow = chunk*32 + r;                  // 0..255
    __shared__ float ac[16*64];
    const float* abase = g_attn + ((size_t)(branch*16 + b)*256)*64;
    const float* wrow  = (branch ? Wc : Wr) + grow*256;
    float sA = (branch ? sc : sr)[grow];
    float bA = (branch ? bc : br)[grow];

    float acc[8];
    #pragma unroll
    for (int j = 0; j < 8; j++) acc[j] = 0.f;

    for (int kc = 0; kc < 16; kc++) {
        #pragma unroll
        for (int t = 0; t < 4; t++) {
            int idx = tid + t*256;
            ac[idx] = abase[(kc*16 + (idx >> 6))*64 + (idx & 63)];
        }
        __syncthreads();
        #pragma unroll
        for (int kk = 0; kk < 16; kk++) {
            float wv = wrow[kc*16 + kk];
            float4 b0 = *(const float4*)&ac[kk*64 + col0];
            float4 b1 = *(const float4*)&ac[kk*64 + col0 + 4];
            acc[0] = fmaf(wv, b0.x, acc[0]); acc[1] = fmaf(wv, b0.y, acc[1]);
            acc[2] = fmaf(wv, b0.z, acc[2]); acc[3] = fmaf(wv, b0.w, acc[3]);
            acc[4] = fmaf(wv, b1.x, acc[4]); acc[5] = fmaf(wv, b1.y, acc[5]);
            acc[6] = fmaf(wv, b1.z, acc[6]); acc[7] = fmaf(wv, b1.w, acc[7]);
        }
        __syncthreads();
    }
    float* dst = g_xrc + ((size_t)((branch*16 + b)*256 + grow))*64 + col0;
    #pragma unroll
    for (int j = 0; j < 8; j++) dst[j] = fmaf(sA, acc[j], bA);
}

// ---------------------------------------------------------------------------
// K3: main fused kernel. One block per (b, h): 64 pixels.
//   Stage1: raw = [Wq;Wk;Wv] @ x      (512x64, K=256), gate-relu into pr,
//           v_raw into xs (overwrites input tile after last use)
//   Stage2: gate = spw*(Wpw @ p)+bpw  (256x64, K=512) -> registers
//   y = relu(v_raw + xr + xc) -> pr[0:256]
//   Stage3: o = sp*(Wp @ y)+bp; out = hsigmoid(o) * gate
// smem: xs 16384 | pr 32768 | wt 16*264 | alpha/beta 1024 | xr 256 floats
// ---------------------------------------------------------------------------
#define OFF_XS 0
#define OFF_PR 16384
#define OFF_WT 49152
#define OFF_AB 53376
#define OFF_XR 54400
#define K3_SMEM_FLOATS 54656
#define K3_SMEM_BYTES (K3_SMEM_FLOATS*4)

__global__ void __launch_bounds__(256, 1) k_main(
    const float* __restrict__ x,
    const float* __restrict__ Wq, const float* __restrict__ Wk, const float* __restrict__ Wv,
    const float* __restrict__ sq, const float* __restrict__ bq,
    const float* __restrict__ sk, const float* __restrict__ bk,
    const float* __restrict__ sv, const float* __restrict__ bv,
    const float* __restrict__ wdw, const float* __restrict__ sdw, const float* __restrict__ bdw,
    const float* __restrict__ Wpw, const float* __restrict__ spw, const float* __restrict__ bpw,
    const float* __restrict__ Wp,  const float* __restrict__ sp,  const float* __restrict__ bp,
    float* __restrict__ out)
{
    extern __shared__ float sm[];
    float* xs  = sm + OFF_XS;   // [256][64] x tile, later v_raw
    float* pr  = sm + OFF_PR;   // [512][64] relu gate input, later [gate-y scratch]
    float* wt  = sm + OFF_WT;   // [16][264] weight k-chunk (transposed, padded)
    float* al  = sm + OFF_AB;   // alpha[512]
    float* be  = al + 512;      // beta[512]
    float* xrs = sm + OFF_XR;   // xr column [256]

    int b = blockIdx.x >> 6;
    int h = blockIdx.x & 63;
    int tid = threadIdx.x;
    int rg = tid >> 3, cg = tid & 7, col0 = cg*8;

    // ---- load x tile + alpha/beta + xr ----
    const float* xb = x + (size_t)(b*256)*NPIX + h*64;
    #pragma unroll 4
    for (int t = 0; t < 64; t++) {
        int idx = tid + t*256;
        xs[idx] = xb[(idx >> 6)*NPIX + (idx & 63)];
    }
    for (int ch = tid; ch < 512; ch += 256) {
        float s, bb;
        if (ch < 128)      { s = sq[ch];     bb = bq[ch]; }
        else if (ch < 256) { s = sk[ch-128]; bb = bk[ch-128]; }
        else               { s = sv[ch-256]; bb = bv[ch-256]; }
        float e = wdw[ch]*sdw[ch];
        al[ch] = e*s;
        be[ch] = fmaf(e, bb, bdw[ch]);
    }
    xrs[tid] = g_xrc[(size_t)(b*256 + tid)*64 + h];     // branch0 slab
    __syncthreads();

    // ================= Stage 1 =================
    for (int pass = 0; pass < 2; pass++) {
        float acc[8][8];
        #pragma unroll
        for (int i2 = 0; i2 < 8; i2++)
            #pragma unroll
            for (int j = 0; j < 8; j++) acc[i2][j] = 0.f;

        for (int kc = 0; kc < 16; kc++) {
            #pragma unroll
            for (int t = 0; t < 16; t++) {
                int idx = tid + t*256;
                int row = idx >> 4, kk = idx & 15;
                int k = kc*16 + kk;
                float wv;
                if (pass == 0) wv = (row < 128) ? Wq[row*256 + k] : Wk[(row-128)*256 + k];
                else           wv = Wv[row*256 + k];
                wt[kk*264 + row] = wv;
            }
            __syncthreads();
            #pragma unroll
            for (int kk = 0; kk < 16; kk++) {
                float4 a0 = *(const float4*)&wt[kk*264 + rg*8];
                float4 a1 = *(const float4*)&wt[kk*264 + rg*8 + 4];
                float4 b0 = *(const float4*)&xs[(kc*16+kk)*64 + col0];
                float4 b1 = *(const float4*)&xs[(kc*16+kk)*64 + col0 + 4];
                float av[8]  = {a0.x,a0.y,a0.z,a0.w,a1.x,a1.y,a1.z,a1.w};
                float bv8[8] = {b0.x,b0.y,b0.z,b0.w,b1.x,b1.y,b1.z,b1.w};
                #pragma unroll
                for (int i2 = 0; i2 < 8; i2++)
                    #pragma unroll
                    for (int j = 0; j < 8; j++)
                        acc[i2][j] = fmaf(av[i2], bv8[j], acc[i2][j]);
            }
            __syncthreads();
        }
        if (pass == 0) {
            #pragma unroll
            for (int i2 = 0; i2 < 8; i2++) {
                int ch = rg*8 + i2;
                float a = al[ch], bb2 = be[ch];
                #pragma unroll
                for (int j = 0; j < 8; j++)
                    pr[ch*64 + col0 + j] = fmaxf(fmaf(a, acc[i2][j], bb2), 0.f);
            }
        } else {
            // all threads are past the chunk-end barrier: safe to overwrite xs
            #pragma unroll
            for (int i2 = 0; i2 < 8; i2++) {
                int lrow = rg*8 + i2;
                int ch = 256 + lrow;
                float a = al[ch], bb2 = be[ch];
                float svv = sv[lrow], bvv = bv[lrow];
                #pragma unroll
                for (int j = 0; j < 8; j++) {
                    float rr = acc[i2][j];
                    pr[ch*64 + col0 + j]   = fmaxf(fmaf(a, rr, bb2), 0.f);
                    xs[lrow*64 + col0 + j] = fmaf(svv, rr, bvv);     // v_raw
                }
            }
        }
        __syncthreads();
    }

    // ================= Stage 2 (gate) =================
    float gacc[8][8];
    #pragma unroll
    for (int i2 = 0; i2 < 8; i2++)
        #pragma unroll
        for (int j = 0; j < 8; j++) gacc[i2][j] = 0.f;

    for (int kc = 0; kc < 32; kc++) {
        #pragma unroll
        for (int t = 0; t < 16; t++) {
            int idx = tid + t*256;
            int row = idx >> 4, kk = idx & 15;
            wt[kk*264 + row] = Wpw[row*512 + kc*16 + kk];
        }
        __syncthreads();
        #pragma unroll
        for (int kk = 0; kk < 16; kk++) {
            float4 a0 = *(const float4*)&wt[kk*264 + rg*8];
            float4 a1 = *(const float4*)&wt[kk*264 + rg*8 + 4];
            float4 b0 = *(const float4*)&pr[(kc*16+kk)*64 + col0];
            float4 b1 = *(const float4*)&pr[(kc*16+kk)*64 + col0 + 4];
            float av[8]  = {a0.x,a0.y,a0.z,a0.w,a1.x,a1.y,a1.z,a1.w};
            float bv8[8] = {b0.x,b0.y,b0.z,b0.w,b1.x,b1.y,b1.z,b1.w};
            #pragma unroll
            for (int i2 = 0; i2 < 8; i2++)
                #pragma unroll
                for (int j = 0; j < 8; j++)
                    gacc[i2][j] = fmaf(av[i2], bv8[j], gacc[i2][j]);
        }
        __syncthreads();
    }
    #pragma unroll
    for (int i2 = 0; i2 < 8; i2++) {
        int row = rg*8 + i2;
        float s = spw[row], bb2 = bpw[row];
        #pragma unroll
        for (int j = 0; j < 8; j++) gacc[i2][j] = fmaf(s, gacc[i2][j], bb2);
    }

    // ---- y = relu(v_raw + xr + xc) into pr[0:256] ----
    const float* xcb = g_xrc + ((size_t)(16 + b)*256)*64;   // branch1 slab
    #pragma unroll
    for (int i2 = 0; i2 < 8; i2++) {
        int c = rg*8 + i2;
        float xr_c = xrs[c];
        #pragma unroll
        for (int j = 0; j < 8; j++) {
            int w = col0 + j;
            pr[c*64 + w] = fmaxf(xs[c*64 + w] + xr_c + xcb[c*64 + w], 0.f);
        }
    }
    __syncthreads();

    // ================= Stage 3 (final proj) =================
    float oacc[8][8];
    #pragma unroll
    for (int i2 = 0; i2 < 8; i2++)
        #pragma unroll
        for (int j = 0; j < 8; j++) oacc[i2][j] = 0.f;

    for (int kc = 0; kc < 16; kc++) {
        #pragma unroll
        for (int t = 0; t < 16; t++) {
            int idx = tid + t*256;
            int row = idx >> 4, kk = idx & 15;
            wt[kk*264 + row] = Wp[row*256 + kc*16 + kk];
        }
        __syncthreads();
        #pragma unroll
        for (int kk = 0; kk < 16; kk++) {
            float4 a0 = *(const float4*)&wt[kk*264 + rg*8];
            float4 a1 = *(const float4*)&wt[kk*264 + rg*8 + 4];
            float4 b0 = *(const float4*)&pr[(kc*16+kk)*64 + col0];
            float4 b1 = *(const float4*)&pr[(kc*16+kk)*64 + col0 + 4];
            float av[8]  = {a0.x,a0.y,a0.z,a0.w,a1.x,a1.y,a1.z,a1.w};
            float bv8[8] = {b0.x,b0.y,b0.z,b0.w,b1.x,b1.y,b1.z,b1.w};
            #pragma unroll
            for (int i2 = 0; i2 < 8; i2++)
                #pragma unroll
                for (int j = 0; j < 8; j++)
                    oacc[i2][j] = fmaf(av[i2], bv8[j], oacc[i2][j]);
        }
        __syncthreads();
    }

    #pragma unroll
    for (int i2 = 0; i2 < 8; i2++) {
        int row = rg*8 + i2;
        float s = sp[row], bb2 = bp[row];
        float* ob = out + (size_t)(b*256 + row)*NPIX + h*64 + col0;
        #pragma unroll
        for (int j = 0; j < 8; j++) {
            float o  = fmaf(s, oacc[i2][j], bb2);
            float hs = fminf(fmaxf(o + 3.f, 0.f), 6.f) * (1.f/6.f);
            ob[j] = hs * gacc[i2][j];
        }
    }
}

// ---------------------------------------------------------------------------
extern "C" void kernel_launch(void* const* d_in, const int* in_sizes, int n_in,
                              void* d_out, int out_size) {
    const float* x     = (const float*)d_in[0];
    const float* Wq    = (const float*)d_in[1];
    const float* sq    = (const float*)d_in[2];
    const float* bq    = (const float*)d_in[3];
    const float* Wk    = (const float*)d_in[4];
    const float* sk    = (const float*)d_in[5];
    const float* bk    = (const float*)d_in[6];
    const float* Wv    = (const float*)d_in[7];
    const float* sv    = (const float*)d_in[8];
    const float* bv    = (const float*)d_in[9];
    const float* pe_rq = (const float*)d_in[10];
    const float* pe_rk = (const float*)d_in[11];
    const float* pe_cq = (const float*)d_in[12];
    const float* pe_ck = (const float*)d_in[13];
    const float* wdw   = (const float*)d_in[14];
    const float* sdw   = (const float*)d_in[15];
    const float* bdw   = (const float*)d_in[16];
    const float* Wpw   = (const float*)d_in[17];
    const float* spw   = (const float*)d_in[18];
    const float* bpw   = (const float*)d_in[19];
    const float* Wr    = (const float*)d_in[20];
    const float* sr    = (const float*)d_in[21];
    const float* br    = (const float*)d_in[22];
    const float* Wc    = (const float*)d_in[23];
    const float* sc    = (const float*)d_in[24];
    const float* bc    = (const float*)d_in[25];
    const float* Wp    = (const float*)d_in[26];
    const float* sp    = (const float*)d_in[27];
    const float* bp    = (const float*)d_in[28];
    float* out = (float*)d_out;

    cudaFuncSetAttribute(k_main, cudaFuncAttributeMaxDynamicSharedMemorySize, K3_SMEM_BYTES);

    k_means<<<4096, 64>>>(x);
    k_projmean<<<dim3(16, 2, 16), 256>>>(Wq, sq, bq, Wk, sk, bk, Wv, sv, bv,
                                         pe_rq, pe_rk, pe_cq, pe_ck);
    k_attn<<<dim3(8, 2, 16), 64>>>();
    k_projattn<<<dim3(8, 2, 16), 256>>>(Wr, sr, br, Wc, sc, bc);
    k_main<<<1024, 256, K3_SMEM_BYTES>>>(x, Wq, Wk, Wv, sq, bq, sk, bk, sv, bv,
                                         wdw, sdw, bdw, Wpw, spw, bpw, Wp, sp, bp, out);
}

// round 3
// speedup vs baseline: 1.8873x; 1.8873x over previous
#include <cuda_runtime.h>
#include <math.h>
#include <stdint.h>

// ---------------------------------------------------------------------------
// ASE block: B=16, DIM=256, H=W=64, KEY_DIM=16, HEADS=8, NH_KD=128, DH=256
//   k_means    : row/col means of x                     -> g_xm
//   k_projmean : q/k/v on means (+scale/bias/pos-embed) -> g_qkm
//   k_attn     : 64-token axial attention (+relu)       -> g_attn
//   k_projattn : Wr / Wc projection                     -> g_xrc
//   k_main     : fused per-pixel pipeline, TF32 tensor-core GEMMs
// ---------------------------------------------------------------------------

#define NPIX 4096
#define SLICE (16*256*64)

__device__ float g_xm  [2*16*256*64];
__device__ float g_qkm [2*16*512*64];
__device__ float g_attn[2*16*256*64];
__device__ float g_xrc [2*16*256*64];

// ---------------------------------------------------------------------------
__global__ void k_means(const float* __restrict__ x) {
    int bc = blockIdx.x;
    const float* xp = x + (size_t)bc * NPIX;
    int t = threadIdx.x;
    int warp = t >> 5, lane = t & 31;
    __shared__ float rowp[64][2];
    float colacc = 0.f;
    for (int h = 0; h < 64; h++) {
        float v = xp[h*64 + t];
        colacc += v;
        float s = v;
        s += __shfl_xor_sync(0xffffffffu, s, 16);
        s += __shfl_xor_sync(0xffffffffu, s, 8);
        s += __shfl_xor_sync(0xffffffffu, s, 4);
        s += __shfl_xor_sync(0xffffffffu, s, 2);
        s += __shfl_xor_sync(0xffffffffu, s, 1);
        if (lane == 0) rowp[h][warp] = s;
    }
    __syncthreads();
    float rm = (rowp[t][0] + rowp[t][1]) * (1.f/64.f);
    g_xm[(size_t)bc*64 + t]         = rm;
    g_xm[SLICE + (size_t)bc*64 + t] = colacc * (1.f/64.f);
}

__device__ __forceinline__ float pe_interp(const float* pe, int chan, int p) {
    float pos = fminf(fmaxf((p + 0.5f)*0.25f - 0.5f, 0.f), 15.f);
    int   i0  = (int)pos;
    int   i1  = min(i0 + 1, 15);
    float w   = pos - (float)i0;
    return pe[chan*16 + i0]*(1.f - w) + pe[chan*16 + i1]*w;
}

// ---------------------------------------------------------------------------
// K2a: project means. grid (32 = 16 rowchunks x 2 colhalves, 2 branch, 16 b)
// ---------------------------------------------------------------------------
__global__ void k_projmean(
    const float* __restrict__ Wq, const float* __restrict__ sq, const float* __restrict__ bq,
    const float* __restrict__ Wk, const float* __restrict__ sk, const float* __restrict__ bk,
    const float* __restrict__ Wv, const float* __restrict__ sv, const float* __restrict__ bv,
    const float* __restrict__ pe_rq, const float* __restrict__ pe_rk,
    const float* __restrict__ pe_cq, const float* __restrict__ pe_ck)
{
    int bx = blockIdx.x;
    int chunk = bx >> 1, half = bx & 1;
    int branch = blockIdx.y;
    int b      = blockIdx.z;
    int tid = threadIdx.x;
    int r = tid >> 3, cg = tid & 7, col0 = half*32 + cg*4;
    int grow = chunk*32 + r;
    __shared__ float xmc[16*64];
    const float* xmbase = g_xm + ((size_t)(branch*16 + b)*256)*64;

    const float* wbase; float sA, bA;
    if (grow < 128)      { wbase = Wq + grow*256;       sA = sq[grow];     bA = bq[grow]; }
    else if (grow < 256) { wbase = Wk + (grow-128)*256; sA = sk[grow-128]; bA = bk[grow-128]; }
    else                 { wbase = Wv + (grow-256)*256; sA = sv[grow-256]; bA = bv[grow-256]; }

    float acc[4] = {0.f, 0.f, 0.f, 0.f};

    for (int kc = 0; kc < 16; kc++) {
        #pragma unroll
        for (int t = 0; t < 4; t++) {
            int idx = tid + t*256;
            xmc[idx] = xmbase[(kc*16 + (idx >> 6))*64 + (idx & 63)];
        }
        __syncthreads();
        #pragma unroll
        for (int kk = 0; kk < 16; kk++) {
            float wv = wbase[kc*16 + kk];
            float4 b0 = *(const float4*)&xmc[kk*64 + col0];
            acc[0] = fmaf(wv, b0.x, acc[0]); acc[1] = fmaf(wv, b0.y, acc[1]);
            acc[2] = fmaf(wv, b0.z, acc[2]); acc[3] = fmaf(wv, b0.w, acc[3]);
        }
        __syncthreads();
    }

    float outv[4];
    #pragma unroll
    for (int j = 0; j < 4; j++) outv[j] = fmaf(sA, acc[j], bA);

    if (grow < 256) {
        const float* pe = (branch == 0) ? ((grow < 128) ? pe_rq : pe_rk)
                                        : ((grow < 128) ? pe_cq : pe_ck);
        int chan = (grow < 128) ? grow : grow - 128;
        #pragma unroll
        for (int j = 0; j < 4; j++) outv[j] += pe_interp(pe, chan, col0 + j);
    }
    float* dst = g_qkm + ((size_t)((branch*16 + b)*512 + grow))*64 + col0;
    #pragma unroll
    for (int j = 0; j < 4; j++) dst[j] = outv[j];
}

// ---------------------------------------------------------------------------
__global__ void k_attn() {
    int head   = blockIdx.x;
    int branch = blockIdx.y;
    int b      = blockIdx.z;
    int i = threadIdx.x;
    __shared__ float kf[16*64];
    __shared__ float vf[32*64];
    const float* base = g_qkm + ((size_t)(branch*16 + b)*512)*64;

    #pragma unroll
    for (int t = 0; t < 16; t++) {
        int idx = i + t*64;
        kf[idx] = base[(128 + head*16 + (idx >> 6))*64 + (idx & 63)];
    }
    #pragma unroll
    for (int t = 0; t < 32; t++) {
        int idx = i + t*64;
        vf[idx] = base[(256 + head*32 + (idx >> 6))*64 + (idx & 63)];
    }
    __syncthreads();

    float qv[16];
    #pragma unroll
    for (int kd = 0; kd < 16; kd++) qv[kd] = base[(head*16 + kd)*64 + i];

    float mx = -1e30f;
    for (int j = 0; j < 64; j++) {
        float s = 0.f;
        #pragma unroll
        for (int kd = 0; kd < 16; kd++) s = fmaf(qv[kd], kf[kd*64 + j], s);
        mx = fmaxf(mx, s * 0.25f);
    }
    float sum = 0.f;
    float facc[32];
    #pragma unroll
    for (int d = 0; d < 32; d++) facc[d] = 0.f;
    for (int j = 0; j < 64; j++) {
        float s = 0.f;
        #pragma unroll
        for (int kd = 0; kd < 16; kd++) s = fmaf(qv[kd], kf[kd*64 + j], s);
        float e = expf(s * 0.25f - mx);
        sum += e;
        #pragma unroll
        for (int d = 0; d < 32; d++) facc[d] = fmaf(e, vf[d*64 + j], facc[d]);
    }
    float inv = 1.f / sum;
    float* dst = g_attn + ((size_t)((branch*16 + b)*256 + head*32))*64 + i;
    #pragma unroll
    for (int d = 0; d < 32; d++) dst[d*64] = fmaxf(facc[d]*inv, 0.f);
}

// ---------------------------------------------------------------------------
// K2c: grid (16 = 8 rowchunks x 2 colhalves, 2 branch, 16 b)
// ---------------------------------------------------------------------------
__global__ void k_projattn(
    const float* __restrict__ Wr, const float* __restrict__ sr, const float* __restrict__ br,
    const float* __restrict__ Wc, const float* __restrict__ sc, const float* __restrict__ bc)
{
    int bx = blockIdx.x;
    int chunk = bx >> 1, half = bx & 1;
    int branch = blockIdx.y;
    int b      = blockIdx.z;
    int tid = threadIdx.x;
    int r = tid >> 3, cg = tid & 7, col0 = half*32 + cg*4;
    int grow = chunk*32 + r;
    __shared__ float ac[16*64];
    const float* abase = g_attn + ((size_t)(branch*16 + b)*256)*64;
    const float* wrow  = (branch ? Wc : Wr) + grow*256;
    float sA = (branch ? sc : sr)[grow];
    float bA = (branch ? bc : br)[grow];

    float acc[4] = {0.f, 0.f, 0.f, 0.f};

    for (int kc = 0; kc < 16; kc++) {
        #pragma unroll
        for (int t = 0; t < 4; t++) {
            int idx = tid + t*256;
            ac[idx] = abase[(kc*16 + (idx >> 6))*64 + (idx & 63)];
        }
        __syncthreads();
        #pragma unroll
        for (int kk = 0; kk < 16; kk++) {
            float wv = wrow[kc*16 + kk];
            float4 b0 = *(const float4*)&ac[kk*64 + col0];
            acc[0] = fmaf(wv, b0.x, acc[0]); acc[1] = fmaf(wv, b0.y, acc[1]);
            acc[2] = fmaf(wv, b0.z, acc[2]); acc[3] = fmaf(wv, b0.w, acc[3]);
        }
        __syncthreads();
    }
    float* dst = g_xrc + ((size_t)((branch*16 + b)*256 + grow))*64 + col0;
    #pragma unroll
    for (int j = 0; j < 4; j++) dst[j] = fmaf(sA, acc[j], bA);
}

// ===========================================================================
// K3: TF32 tensor-core fused main kernel.
// One block per (b,h): M = 64 pixels, per-pass N = 256 out-channels.
// A operand (activations): smem [pixel][k] stride 260  (bank = 4g+tig, CF)
// B operand (weights^T)  : smem [n][kpad=20], DOUBLE-BUFFERED: one barrier
//                          per K-chunk, STS/LDG overlap MMA.
// C layout [pixel][ch] == next stage's A layout. Stage2 (K=512) split into
// two K=256 halves with gate accumulator kept in registers.
// ===========================================================================
#define XSTR 260
#define WPAD 20
#define WBUF 5120         // 256*20 floats per buffer
#define OFF_X  0          // [64][260] x (tf32), later v_raw (fp32)
#define OFF_P  16640      // [64][260] stage outputs (tf32)
#define OFF_W  33280      // 2 x [256][20] weight chunk (tf32)
#define OFF_AL 43520      // alpha[512]
#define OFF_BE 44032      // beta[512]
#define OFF_XR 44544      // xr[256]
#define K3_SMEM_FLOATS 44800
#define K3_SMEM_BYTES (K3_SMEM_FLOATS*4)

__device__ __forceinline__ float tf32r(float x) {
    uint32_t u;
    asm("cvt.rna.tf32.f32 %0, %1;" : "=r"(u) : "f"(x));
    return __uint_as_float(u);
}

__device__ __forceinline__ void wload(float4 pf[4], const float* W0, const float* W1,
                                      int kstride, int k0, int quad, int nb) {
    #pragma unroll
    for (int r = 0; r < 4; r++) {
        int n = nb + r*64;
        const float* base = (r < 2) ? (W0 + (size_t)n*kstride)
                                    : (W1 + (size_t)(n-128)*kstride);
        pf[r] = *(const float4*)(base + k0 + quad*4);
    }
}

__device__ __forceinline__ void wstore(const float4 pf[4], float* sWb, int quad, int nb) {
    #pragma unroll
    for (int r = 0; r < 4; r++) {
        int n = nb + r*64;
        float4 v;
        v.x = tf32r(pf[r].x); v.y = tf32r(pf[r].y);
        v.z = tf32r(pf[r].z); v.w = tf32r(pf[r].w);
        *(float4*)&sWb[n*WPAD + quad*4] = v;
    }
}

__device__ __forceinline__ void gemm_iter(const float* A, const float* sWb,
                                          int nw, int g, int tig,
                                          float (&acc)[4][4][4]) {
    #pragma unroll
    for (int ks2 = 0; ks2 < 2; ks2++) {
        int kk = ks2*8;
        uint32_t a[4][4];
        #pragma unroll
        for (int m = 0; m < 4; m++) {
            int r0 = m*16 + g;
            a[m][0] = __float_as_uint(A[r0*XSTR + kk + tig]);
            a[m][1] = __float_as_uint(A[(r0+8)*XSTR + kk + tig]);
            a[m][2] = __float_as_uint(A[r0*XSTR + kk + tig + 4]);
            a[m][3] = __float_as_uint(A[(r0+8)*XSTR + kk + tig + 4]);
        }
        #pragma unroll
        for (int nt = 0; nt < 4; nt++) {
            int n0 = nw + nt*8;
            uint32_t b0 = __float_as_uint(sWb[(n0+g)*WPAD + kk + tig]);
            uint32_t b1 = __float_as_uint(sWb[(n0+g)*WPAD + kk + tig + 4]);
            #pragma unroll
            for (int m = 0; m < 4; m++) {
                asm volatile(
                    "mma.sync.aligned.m16n8k8.row.col.f32.tf32.tf32.f32 "
                    "{%0,%1,%2,%3}, {%4,%5,%6,%7}, {%8,%9}, {%0,%1,%2,%3};"
                    : "+f"(acc[m][nt][0]), "+f"(acc[m][nt][1]),
                      "+f"(acc[m][nt][2]), "+f"(acc[m][nt][3])
                    : "r"(a[m][0]), "r"(a[m][1]), "r"(a[m][2]), "r"(a[m][3]),
                      "r"(b0), "r"(b1));
            }
        }
    }
}

// 16 K-chunks (K=256), double-buffered weights: 1 barrier per chunk.
__device__ __forceinline__ void run_gemm(const float* A,
                                         const float* W0, const float* W1, int kstride,
                                         float* sW, float (&acc)[4][4][4],
                                         int tid, int nw, int g, int tig) {
    int quad = tid & 3, nb = tid >> 2;
    float4 pf[4];
    wload(pf, W0, W1, kstride, 0, quad, nb);
    wstore(pf, sW, quad, nb);                       // buf0 <- chunk0
    wload(pf, W0, W1, kstride, 16, quad, nb);       // prefetch chunk1
    __syncthreads();
    #pragma unroll 1
    for (int it = 0; it < 16; it++) {
        float* cur = sW + (it & 1)*WBUF;
        if (it < 15) {
            wstore(pf, sW + ((it + 1) & 1)*WBUF, quad, nb);
            if (it < 14) wload(pf, W0, W1, kstride, (it + 2)*16, quad, nb);
        }
        gemm_iter(A + it*16, cur, nw, g, tig, acc);
        __syncthreads();
    }
}

__global__ void __launch_bounds__(256, 1) k_main(
    const float* __restrict__ x,
    const float* __restrict__ Wq, const float* __restrict__ Wk, const float* __restrict__ Wv,
    const float* __restrict__ sq, const float* __restrict__ bq,
    const float* __restrict__ sk, const float* __restrict__ bk,
    const float* __restrict__ sv, const float* __restrict__ bv,
    const float* __restrict__ wdw, const float* __restrict__ sdw, const float* __restrict__ bdw,
    const float* __restrict__ Wpw, const float* __restrict__ spw, const float* __restrict__ bpw,
    const float* __restrict__ Wp,  const float* __restrict__ sp,  const float* __restrict__ bp,
    float* __restrict__ out)
{
    extern __shared__ float sm[];
    float* sX  = sm + OFF_X;
    float* sP  = sm + OFF_P;
    float* sW  = sm + OFF_W;
    float* al  = sm + OFF_AL;
    float* be  = sm + OFF_BE;
    float* xrs = sm + OFF_XR;

    int b = blockIdx.x >> 6;
    int h = blockIdx.x & 63;
    int tid = threadIdx.x;
    int lane = tid & 31, warp = tid >> 5;
    int g = lane >> 2, tig = lane & 3;
    int nw = warp * 32;

    // ---- load x tile (transposed to [pixel][c], tf32) + al/be + xr ----
    const float* xb = x + (size_t)b*256*NPIX + h*64;
    #pragma unroll 4
    for (int t = 0; t < 64; t++) {
        int idx = tid + t*256;
        int c = idx >> 6, w = idx & 63;
        sX[w*XSTR + c] = tf32r(xb[c*NPIX + w]);
    }
    for (int ch = tid; ch < 512; ch += 256) {
        float s, bb;
        if (ch < 128)      { s = sq[ch];     bb = bq[ch]; }
        else if (ch < 256) { s = sk[ch-128]; bb = bk[ch-128]; }
        else               { s = sv[ch-256]; bb = bv[ch-256]; }
        float e = wdw[ch]*sdw[ch];
        al[ch] = e*s;
        be[ch] = fmaf(e, bb, bdw[ch]);
    }
    xrs[tid] = g_xrc[((size_t)b*256 + tid)*64 + h];
    __syncthreads();

    float acc[4][4][4];
    float gacc[4][4][4];
    #pragma unroll
    for (int m = 0; m < 4; m++)
        #pragma unroll
        for (int nt = 0; nt < 4; nt++)
            #pragma unroll
            for (int e = 0; e < 4; e++) { acc[m][nt][e] = 0.f; gacc[m][nt][e] = 0.f; }

    // ========== stage1 pass1: qk rows (out 0..255), A = x ==========
    run_gemm(sX, Wq, Wk, 256, sW, acc, tid, nw, g, tig);
    #pragma unroll
    for (int m = 0; m < 4; m++)
        #pragma unroll
        for (int nt = 0; nt < 4; nt++) {
            int ch = nw + nt*8 + 2*tig;
            int p0 = m*16 + g;
            #pragma unroll
            for (int e = 0; e < 4; e++) {
                int che = ch + (e & 1);
                int pe  = p0 + ((e >> 1) << 3);
                sP[pe*XSTR + che] = tf32r(fmaxf(fmaf(al[che], acc[m][nt][e], be[che]), 0.f));
            }
        }
    __syncthreads();

    // ========== stage2a: gate += P_qk @ Wpw[:, 0:256]^T ==========
    run_gemm(sP, Wpw, Wpw + (size_t)128*512, 512, sW, gacc, tid, nw, g, tig);

    // ========== stage1 pass2: v rows, A = x ==========
    #pragma unroll
    for (int m = 0; m < 4; m++)
        #pragma unroll
        for (int nt = 0; nt < 4; nt++)
            #pragma unroll
            for (int e = 0; e < 4; e++) acc[m][nt][e] = 0.f;
    run_gemm(sX, Wv, Wv + (size_t)128*256, 256, sW, acc, tid, nw, g, tig);
    #pragma unroll
    for (int m = 0; m < 4; m++)
        #pragma unroll
        for (int nt = 0; nt < 4; nt++) {
            int ch = nw + nt*8 + 2*tig;
            int p0 = m*16 + g;
            #pragma unroll
            for (int e = 0; e < 4; e++) {
                int che = ch + (e & 1);
                int pe  = p0 + ((e >> 1) << 3);
                float rr = acc[m][nt][e];
                sP[pe*XSTR + che] = tf32r(fmaxf(fmaf(al[256+che], rr, be[256+che]), 0.f));
                sX[pe*XSTR + che] = fmaf(sv[che], rr, bv[che]);   // v_raw (fp32)
            }
        }
    __syncthreads();

    // ========== stage2b: gate += P_v @ Wpw[:, 256:512]^T ==========
    run_gemm(sP, Wpw + 256, Wpw + (size_t)128*512 + 256, 512, sW, gacc, tid, nw, g, tig);

    // ========== y = relu(v_raw + xr + xc) -> P ==========
    const float* xcb = g_xrc + ((size_t)(16 + b))*16384;
    #pragma unroll 4
    for (int t = 0; t < 64; t++) {
        int idx = tid + t*256;
        int w = idx & 63, ch = idx >> 6;
        float y = fmaxf(sX[w*XSTR + ch] + xrs[ch] + xcb[ch*64 + w], 0.f);
        sP[w*XSTR + ch] = tf32r(y);
    }
    __syncthreads();

    // ========== stage3: o = Y @ Wp^T ==========
    #pragma unroll
    for (int m = 0; m < 4; m++)
        #pragma unroll
        for (int nt = 0; nt < 4; nt++)
            #pragma unroll
            for (int e = 0; e < 4; e++) acc[m][nt][e] = 0.f;
    run_gemm(sP, Wp, Wp + (size_t)128*256, 256, sW, acc, tid, nw, g, tig);

    // ========== final epilogue: hsigmoid(sp*o+bp) * (spw*gate+bpw) ==========
    #pragma unroll
    for (int m = 0; m < 4; m++)
        #pragma unroll
        for (int nt = 0; nt < 4; nt++) {
            int ch = nw + nt*8 + 2*tig;
            int p0 = m*16 + g;
            float s0 = sp[ch],  s1 = sp[ch+1];
            float bb0 = bp[ch], bb1 = bp[ch+1];
            float gs0 = spw[ch], gs1 = spw[ch+1];
            float gb0 = bpw[ch], gb1 = bpw[ch+1];
            #pragma unroll
            for (int e = 0; e < 4; e++) {
                int odd = e & 1;
                int che = ch + odd;
                int pe  = p0 + ((e >> 1) << 3);
                float o  = fmaf(odd ? s1 : s0, acc[m][nt][e], odd ? bb1 : bb0);
                float hs = fminf(fmaxf(o + 3.f, 0.f), 6.f) * (1.f/6.f);
                float gt = fmaf(odd ? gs1 : gs0, gacc[m][nt][e], odd ? gb1 : gb0);
                out[((size_t)(b*256 + che))*NPIX + h*64 + pe] = hs * gt;
            }
        }
}

// ---------------------------------------------------------------------------
extern "C" void kernel_launch(void* const* d_in, const int* in_sizes, int n_in,
                              void* d_out, int out_size) {
    const float* x     = (const float*)d_in[0];
    const float* Wq    = (const float*)d_in[1];
    const float* sq    = (const float*)d_in[2];
    const float* bq    = (const float*)d_in[3];
    const float* Wk    = (const float*)d_in[4];
    const float* sk    = (const float*)d_in[5];
    const float* bk    = (const float*)d_in[6];
    const float* Wv    = (const float*)d_in[7];
    const float* sv    = (const float*)d_in[8];
    const float* bv    = (const float*)d_in[9];
    const float* pe_rq = (const float*)d_in[10];
    const float* pe_rk = (const float*)d_in[11];
    const float* pe_cq = (const float*)d_in[12];
    const float* pe_ck = (const float*)d_in[13];
    const float* wdw   = (const float*)d_in[14];
    const float* sdw   = (const float*)d_in[15];
    const float* bdw   = (const float*)d_in[16];
    const float* Wpw   = (const float*)d_in[17];
    const float* spw   = (const float*)d_in[18];
    const float* bpw   = (const float*)d_in[19];
    const float* Wr    = (const float*)d_in[20];
    const float* sr    = (const float*)d_in[21];
    const float* br    = (const float*)d_in[22];
    const float* Wc    = (const float*)d_in[23];
    const float* sc    = (const float*)d_in[24];
    const float* bc    = (const float*)d_in[25];
    const float* Wp    = (const float*)d_in[26];
    const float* sp    = (const float*)d_in[27];
    const float* bp    = (const float*)d_in[28];
    float* out = (float*)d_out;

    cudaFuncSetAttribute(k_main, cudaFuncAttributeMaxDynamicSharedMemorySize, K3_SMEM_BYTES);

    k_means<<<4096, 64>>>(x);
    k_projmean<<<dim3(32, 2, 16), 256>>>(Wq, sq, bq, Wk, sk, bk, Wv, sv, bv,
                                         pe_rq, pe_rk, pe_cq, pe_ck);
    k_attn<<<dim3(8, 2, 16), 64>>>();
    k_projattn<<<dim3(16, 2, 16), 256>>>(Wr, sr, br, Wc, sc, bc);
    k_main<<<1024, 256, K3_SMEM_BYTES>>>(x, Wq, Wk, Wv, sq, bq, sk, bk, sv, bv,
                                         wdw, sdw, bdw, Wpw, spw, bpw, Wp, sp, bp, out);
}